// round 2
// baseline (speedup 1.0000x reference)
#include <cuda_runtime.h>

#define BATCH 4
#define EDIM 1024
#define CDIM 768
#define TLEN 1024
#define SLEN 1024
#define NH 16
#define DH 64
#define EPSV 1e-5f

// ---------------- scratch (static device globals; no allocation) ----------------
__device__ float g_wnq[EDIM * EDIM];
__device__ float g_wnk[EDIM * CDIM];
__device__ float g_wnv[EDIM * CDIM];
__device__ float g_wno[EDIM * EDIM];
__device__ float g_q[BATCH * EDIM * TLEN];
__device__ float g_k[BATCH * EDIM * SLEN];
__device__ float g_v[BATCH * EDIM * SLEN];
__device__ float g_p[(long)BATCH * NH * SLEN * TLEN];   // 256 MB score/prob scratch
__device__ float g_att[BATCH * EDIM * TLEN];
__device__ unsigned char g_mask[BATCH * TLEN];
__device__ unsigned char g_mctx[BATCH * SLEN];

// ---------------- mask canonicalization (dtype-agnostic: bool-bytes or int32) ----
// Single block. Inspect first n bytes (safe for either layout: int32 buffer is 4n
// bytes, bool buffer is n bytes). int32 0/1 data has ALL bytes at i%4!=0 equal to
// zero; bool data has random nonzeros there. Then emit canonical uint8 mask.
__global__ void canon_mask_kernel(const unsigned char* __restrict__ raw,
                                  unsigned char* __restrict__ out, int n) {
    __shared__ int s_flag;
    if (threadIdx.x == 0) s_flag = 0;
    __syncthreads();
    int local = 0;
    for (int i = threadIdx.x; i < n; i += blockDim.x)
        if ((i & 3) != 0 && raw[i] != 0) local = 1;
    if (local) atomicOr(&s_flag, 1);
    __syncthreads();
    bool is_bool = (s_flag != 0);
    for (int i = threadIdx.x; i < n; i += blockDim.x)
        out[i] = is_bool ? raw[i] : raw[4 * i];
}

// ---------------- weight standardization: per output row over I ----------------
__global__ void ws_kernel(const float* __restrict__ w, float* __restrict__ out, int I) {
    int o = blockIdx.x;
    const float* row = w + (long)o * I;
    float s = 0.f, ss = 0.f;
    for (int i = threadIdx.x; i < I; i += 256) {
        float v = row[i];
        s += v;
        ss += v * v;
    }
#pragma unroll
    for (int off = 16; off; off >>= 1) {
        s += __shfl_xor_sync(0xFFFFFFFFu, s, off);
        ss += __shfl_xor_sync(0xFFFFFFFFu, ss, off);
    }
    __shared__ float sh[16];
    int wid = threadIdx.x >> 5;
    if ((threadIdx.x & 31) == 0) { sh[wid] = s; sh[8 + wid] = ss; }
    __syncthreads();
    if (threadIdx.x == 0) {
        float ts = 0.f, tss = 0.f;
        for (int i = 0; i < 8; i++) { ts += sh[i]; tss += sh[8 + i]; }
        float mu = ts / (float)I;
        float var = tss / (float)I - mu * mu;
        sh[0] = mu;
        sh[1] = rsqrtf(var + EPSV);
    }
    __syncthreads();
    float mu = sh[0], inv = sh[1];
    for (int i = threadIdx.x; i < I; i += 256)
        out[(long)o * I + i] = (row[i] - mu) * inv;
}

// ---------------- generic register-tiled fp32 GEMM ----------------
// C[m,n] = sum_k Aop[k,m or m,k] * B[k,n]   (per-z batch via strides)
// EPI 0: conv  -> c += bias[m]; if(!mask[col]) c=0; if(res) c += res
// EPI 1: score -> c = mask[col] ? c*scale : -1e9
// EPI 2: plain
template <int BM, bool TRANSA, int EPI>
__global__ __launch_bounds__(256) void gemm_kernel(
    const float* __restrict__ A0, long aStride, int lda,
    const float* __restrict__ B0, long bStride, int ldb,
    float* __restrict__ C0, long cStride, int ldc,
    int K,
    const float* __restrict__ bias,
    const unsigned char* __restrict__ mask, int maskDiv, int maskLd,
    const float* __restrict__ res, long resStride,
    float scale)
{
    constexpr int TM = BM / 16;   // per-thread M microtile (4 or 8)
    int z = blockIdx.z;
    const float* A = A0 + (long)z * aStride;
    const float* Bm = B0 + (long)z * bStride;
    float* C = C0 + (long)z * cStride;
    int mBase = blockIdx.y * BM, nBase = blockIdx.x * 64;

    __shared__ float As[16][BM];
    __shared__ float Bs[16][64];

    int tid = threadIdx.x;
    int tx = tid & 15, ty = tid >> 4;

    float acc[TM][4];
#pragma unroll
    for (int i = 0; i < TM; i++)
#pragma unroll
        for (int j = 0; j < 4; j++) acc[i][j] = 0.f;

    for (int k0 = 0; k0 < K; k0 += 16) {
        if (TRANSA) {
            // A is [K, M] (lda = M-stride). Vectorized, coalesced.
#pragma unroll
            for (int r = 0; r < BM / 64; r++) {
                int v = tid + 256 * r;
                int k = v / (BM / 4);
                int mq = (v % (BM / 4)) * 4;
                *(float4*)&As[k][mq] =
                    *(const float4*)&A[(long)(k0 + k) * lda + mBase + mq];
            }
        } else {
            // A is [M, K] row-major; transpose into As[k][m].
#pragma unroll
            for (int r = 0; r < BM / 64; r++) {
                int v = tid + 256 * r;
                int m = v >> 2;
                int kq = (v & 3) * 4;
                float4 a = *(const float4*)&A[(long)(mBase + m) * lda + k0 + kq];
                As[kq + 0][m] = a.x;
                As[kq + 1][m] = a.y;
                As[kq + 2][m] = a.z;
                As[kq + 3][m] = a.w;
            }
        }
        {
            int k = tid >> 4;
            int nq = (tid & 15) * 4;
            *(float4*)&Bs[k][nq] =
                *(const float4*)&Bm[(long)(k0 + k) * ldb + nBase + nq];
        }
        __syncthreads();
#pragma unroll
        for (int kk = 0; kk < 16; kk++) {
            float b[4];
            *(float4*)b = *(const float4*)&Bs[kk][tx * 4];
            float a[TM];
#pragma unroll
            for (int u = 0; u < TM / 4; u++)
                *(float4*)&a[u * 4] = *(const float4*)&As[kk][ty * TM + u * 4];
#pragma unroll
            for (int i = 0; i < TM; i++)
#pragma unroll
                for (int j = 0; j < 4; j++)
                    acc[i][j] += a[i] * b[j];
        }
        __syncthreads();
    }

    int mb = z / maskDiv;
#pragma unroll
    for (int i = 0; i < TM; i++) {
        int m = mBase + ty * TM + i;
        float bv = (EPI == 0) ? bias[m] : 0.f;
#pragma unroll
        for (int j = 0; j < 4; j++) {
            int n = nBase + tx * 4 + j;
            float c = acc[i][j];
            if (EPI == 0) {
                c += bv;
                if (!mask[(long)mb * maskLd + n]) c = 0.f;
                if (res) c += res[(long)z * resStride + (long)m * ldc + n];
            } else if (EPI == 1) {
                c = mask[(long)mb * maskLd + n] ? c * scale : -1e9f;
            }
            C[(long)m * ldc + n] = c;
        }
    }
}

// ---------------- per-head LayerNorm over dh=64 ----------------
// buf: [B*H, DH, L]; one thread per (bh, l) column, loop d (coalesced across threads)
__global__ void ln_kernel(float* __restrict__ buf, const float* __restrict__ g,
                          const float* __restrict__ bt, int L) {
    int bh = blockIdx.y;
    int l = blockIdx.x * blockDim.x + threadIdx.x;
    float* base = buf + (long)bh * DH * L + l;
    float vals[DH];
    float s = 0.f, ss = 0.f;
#pragma unroll
    for (int d = 0; d < DH; d++) {
        float v = base[(long)d * L];
        vals[d] = v;
        s += v;
        ss += v * v;
    }
    float mu = s * (1.f / DH);
    float var = ss * (1.f / DH) - mu * mu;
    float inv = rsqrtf(var + EPSV);
#pragma unroll
    for (int d = 0; d < DH; d++)
        base[(long)d * L] = (vals[d] - mu) * inv * g[d] + bt[d];
}

// ---------------- softmax over T per (b,h,s) row + ctx-mask zeroing ----------------
__global__ void softmax_kernel(float* __restrict__ sc,
                               const unsigned char* __restrict__ mctx) {
    long row = blockIdx.x;           // [0, B*H*S)
    int b = (int)(row / (NH * SLEN));
    int s = (int)(row % SLEN);
    float* p = sc + row * (long)TLEN;
    int t = threadIdx.x;             // 128 threads, 8 elems each
    float v[8];
    float m = -3.0e38f;
#pragma unroll
    for (int r = 0; r < 8; r++) {
        v[r] = p[t + r * 128];
        m = fmaxf(m, v[r]);
    }
#pragma unroll
    for (int off = 16; off; off >>= 1)
        m = fmaxf(m, __shfl_xor_sync(0xFFFFFFFFu, m, off));
    __shared__ float sm[4], ssum[4];
    if ((t & 31) == 0) sm[t >> 5] = m;
    __syncthreads();
    m = fmaxf(fmaxf(sm[0], sm[1]), fmaxf(sm[2], sm[3]));
    float sum = 0.f;
#pragma unroll
    for (int r = 0; r < 8; r++) {
        v[r] = expf(v[r] - m);
        sum += v[r];
    }
#pragma unroll
    for (int off = 16; off; off >>= 1)
        sum += __shfl_xor_sync(0xFFFFFFFFu, sum, off);
    if ((t & 31) == 0) ssum[t >> 5] = sum;
    __syncthreads();
    sum = ssum[0] + ssum[1] + ssum[2] + ssum[3];
    float inv = (mctx[(long)b * SLEN + s] && sum > 0.f) ? (1.f / sum) : 0.f;
#pragma unroll
    for (int r = 0; r < 8; r++)
        p[t + r * 128] = v[r] * inv;
}

// ---------------- launch ----------------
extern "C" void kernel_launch(void* const* d_in, const int* in_sizes, int n_in,
                              void* d_out, int out_size) {
    const float* x = (const float*)d_in[0];
    const float* ctx = (const float*)d_in[1];
    const unsigned char* mask_raw = (const unsigned char*)d_in[2];
    const unsigned char* mctx_raw = (const unsigned char*)d_in[3];
    const float* qw = (const float*)d_in[4];
    const float* qb = (const float*)d_in[5];
    const float* kw = (const float*)d_in[6];
    const float* kb = (const float*)d_in[7];
    const float* vw = (const float*)d_in[8];
    const float* vb = (const float*)d_in[9];
    const float* ow = (const float*)d_in[10];
    const float* ob = (const float*)d_in[11];
    const float* gq = (const float*)d_in[12];
    const float* bq = (const float*)d_in[13];
    const float* gk = (const float*)d_in[14];
    const float* bk = (const float*)d_in[15];
    const float* gv = (const float*)d_in[16];
    const float* bv = (const float*)d_in[17];
    float* out = (float*)d_out;

    float *wnq, *wnk, *wnv, *wno, *qbuf, *kbuf, *vbuf, *pbuf, *abuf;
    unsigned char *mask, *mctx;
    cudaGetSymbolAddress((void**)&wnq, g_wnq);
    cudaGetSymbolAddress((void**)&wnk, g_wnk);
    cudaGetSymbolAddress((void**)&wnv, g_wnv);
    cudaGetSymbolAddress((void**)&wno, g_wno);
    cudaGetSymbolAddress((void**)&qbuf, g_q);
    cudaGetSymbolAddress((void**)&kbuf, g_k);
    cudaGetSymbolAddress((void**)&vbuf, g_v);
    cudaGetSymbolAddress((void**)&pbuf, g_p);
    cudaGetSymbolAddress((void**)&abuf, g_att);
    cudaGetSymbolAddress((void**)&mask, g_mask);
    cudaGetSymbolAddress((void**)&mctx, g_mctx);

    // 0. canonicalize masks (handles bool-byte or int32 storage)
    canon_mask_kernel<<<1, 256>>>(mask_raw, mask, BATCH * TLEN);
    canon_mask_kernel<<<1, 256>>>(mctx_raw, mctx, BATCH * SLEN);

    // 1. weight standardization
    ws_kernel<<<EDIM, 256>>>(qw, wnq, EDIM);
    ws_kernel<<<EDIM, 256>>>(kw, wnk, CDIM);
    ws_kernel<<<EDIM, 256>>>(vw, wnv, CDIM);
    ws_kernel<<<EDIM, 256>>>(ow, wno, EDIM);

    // 2. QKV projections (WS conv epilogue: bias + column mask -> 0)
    dim3 gconv(TLEN / 64, EDIM / 128, BATCH);
    gemm_kernel<128, false, 0><<<gconv, 256>>>(
        wnq, 0, EDIM, x, (long)EDIM * TLEN, TLEN,
        qbuf, (long)EDIM * TLEN, TLEN, EDIM,
        qb, mask, 1, TLEN, nullptr, 0, 1.f);
    gemm_kernel<128, false, 0><<<gconv, 256>>>(
        wnk, 0, CDIM, ctx, (long)CDIM * SLEN, SLEN,
        kbuf, (long)EDIM * SLEN, SLEN, CDIM,
        kb, mctx, 1, SLEN, nullptr, 0, 1.f);
    gemm_kernel<128, false, 0><<<gconv, 256>>>(
        wnv, 0, CDIM, ctx, (long)CDIM * SLEN, SLEN,
        vbuf, (long)EDIM * SLEN, SLEN, CDIM,
        vb, mctx, 1, SLEN, nullptr, 0, 1.f);

    // 3. per-head LayerNorm over dh
    dim3 gln(TLEN / 128, BATCH * NH);
    ln_kernel<<<gln, 128>>>(qbuf, gq, bq, TLEN);
    ln_kernel<<<gln, 128>>>(kbuf, gk, bk, SLEN);
    ln_kernel<<<gln, 128>>>(vbuf, gv, bv, SLEN);

    // 4. scores[s,t] = sum_d k[d,s] q[d,t] / 256, t-mask -> -1e9
    dim3 gsc(TLEN / 64, SLEN / 128, BATCH * NH);
    gemm_kernel<128, true, 1><<<gsc, 256>>>(
        kbuf, (long)DH * SLEN, SLEN, qbuf, (long)DH * TLEN, TLEN,
        pbuf, (long)SLEN * TLEN, TLEN, DH,
        nullptr, mask, NH, TLEN, nullptr, 0, 1.f / 256.f);

    // 5. softmax over T per (b,h,s), then zero rows where !mask_ctx[s]
    softmax_kernel<<<BATCH * NH * SLEN, 128>>>(pbuf, mctx);

    // 6. out[d,t] = sum_s v[d,s] P[s,t]
    dim3 gav(TLEN / 64, 1, BATCH * NH);
    gemm_kernel<64, false, 2><<<gav, 256>>>(
        vbuf, (long)DH * SLEN, SLEN, pbuf, (long)SLEN * TLEN, TLEN,
        abuf, (long)DH * TLEN, TLEN, SLEN,
        nullptr, nullptr, 1, 0, nullptr, 0, 1.f);

    // 7. output projection: WS conv + bias + mask->0 + residual x
    gemm_kernel<128, false, 0><<<gconv, 256>>>(
        wno, 0, EDIM, abuf, (long)EDIM * TLEN, TLEN,
        out, (long)EDIM * TLEN, TLEN, EDIM,
        ob, mask, 1, TLEN, x, (long)EDIM * TLEN, 1.f);
}

// round 4
// speedup vs baseline: 1.6720x; 1.6720x over previous
#include <cuda_runtime.h>
#include <cstdint>

#define BATCH 4
#define EDIM 1024
#define CDIM 768
#define TLEN 1024
#define SLEN 1024
#define NH 16
#define DH 64
#define EPSV 1e-5f

// ---------------- scratch (static device globals; no allocation) ----------------
__device__ float g_wnq[EDIM * EDIM];
__device__ float g_wnk[EDIM * CDIM];
__device__ float g_wnv[EDIM * CDIM];
__device__ float g_wno[EDIM * EDIM];
__device__ float g_q[BATCH * EDIM * TLEN];
__device__ float g_k[BATCH * EDIM * SLEN];
__device__ float g_v[BATCH * EDIM * SLEN];
__device__ float g_p[(long)BATCH * NH * SLEN * TLEN];   // 256 MB score/prob scratch
__device__ float g_att[BATCH * EDIM * TLEN];            // att^T: [B][T][E]
__device__ unsigned char g_mask[BATCH * TLEN];
__device__ unsigned char g_mctx[BATCH * SLEN];

__device__ __forceinline__ float to_tf32(float x) {
    float r;
    asm("cvt.rna.tf32.f32 %0, %1;" : "=f"(r) : "f"(x));
    return r;
}
__device__ __forceinline__ uint32_t f2u(float x) { return __float_as_uint(x); }

#define MMA_TF32(d, a, b) \
    asm volatile("mma.sync.aligned.m16n8k8.row.col.f32.tf32.tf32.f32 " \
                 "{%0,%1,%2,%3}, {%4,%5,%6,%7}, {%8,%9}, {%0,%1,%2,%3};" \
                 : "+f"((d)[0]), "+f"((d)[1]), "+f"((d)[2]), "+f"((d)[3]) \
                 : "r"((a)[0]), "r"((a)[1]), "r"((a)[2]), "r"((a)[3]), \
                   "r"((b)[0]), "r"((b)[1]))

// ================= mma.sync TF32 GEMM =================
// C[m,n] = sum_k A'[m,k] * B'[n,k]
//   A' from src [m,k] (TA=false) or [k,m] (TA=true)
//   B' from src [n,k] (TB=false) or [k,n] (TB=true)
// EPI 0: conv (bias + col-mask->0 + optional residual); 1: score (mask? c*scale : -1e9); 2: plain
// Block: 256 thr, tile BM=128 x BN, BK=32, double-buffered SMEM.
template <int EPI, bool TA, bool TB, int BN>
__global__ __launch_bounds__(256) void mma_gemm(
    const float* __restrict__ A0, long aStride, int lda,
    const float* __restrict__ B0, long bStride, int ldb,
    float* __restrict__ C0, int zDiv, long cStrZa, long cStrZb, int ldc,
    int K,
    const float* __restrict__ bias,
    const unsigned char* __restrict__ mask, int maskDiv, int maskLd,
    const float* __restrict__ res, long resStride, float scale)
{
    constexpr int BM = 128;
    constexpr int ASTR = 136;            // As[k][m], 32 x 136 floats
    constexpr int BSTR = 36;             // Bs[n][k], BN x 36 floats
    constexpr int AF = 32 * ASTR;        // floats per A stage
    constexpr int BF = BN * BSTR;
    constexpr int STG = AF + BF;
    constexpr int NAR = 4;               // A float4 loads per thread
    constexpr int NBR = BN / 32;         // B float4 loads per thread
    constexpr int WN = BN / 2;           // warp tile N (warps 4x2)
    constexpr int NF = WN / 8;

    extern __shared__ float smf[];
    int tid = threadIdx.x, wid = tid >> 5, lane = tid & 31;
    int z = blockIdx.z;
    const float* A = A0 + z * aStride;
    const float* B = B0 + z * bStride;
    float* C = C0 + (z / zDiv) * cStrZa + (z % zDiv) * cStrZb;
    long mBase = (long)blockIdx.y * BM, nBase = (long)blockIdx.x * BN;

    float acc[2][NF][4];
#pragma unroll
    for (int i = 0; i < 2; ++i)
#pragma unroll
        for (int j = 0; j < NF; ++j)
#pragma unroll
            for (int t = 0; t < 4; ++t) acc[i][j][t] = 0.f;

    float4 ra[NAR], rb[NBR];
    int nIter = K / 32;

    // ---- index helpers (must match between LDG and STS) ----
    auto ldgA = [&](int k0) {
#pragma unroll
        for (int r = 0; r < NAR; ++r) {
            int lin = tid + 256 * r;
            if (TA) {
                int k = lin >> 5, mq = (lin & 31) * 4;
                ra[r] = *(const float4*)&A[(long)(k0 + k) * lda + mBase + mq];
            } else {
                int m = lin >> 3, kq = (lin & 7) * 4;
                ra[r] = *(const float4*)&A[(mBase + m) * (long)lda + k0 + kq];
            }
        }
    };
    auto ldgB = [&](int k0) {
#pragma unroll
        for (int r = 0; r < NBR; ++r) {
            int lin = tid + 256 * r;
            if (TB) {
                constexpr int NQ = BN / 4;
                int k = lin / NQ, nq = (lin % NQ) * 4;
                rb[r] = *(const float4*)&B[(long)(k0 + k) * ldb + nBase + nq];
            } else {
                int n = lin >> 3, kq = (lin & 7) * 4;
                rb[r] = *(const float4*)&B[(nBase + n) * (long)ldb + k0 + kq];
            }
        }
    };
    auto stsA = [&](float* As) {
#pragma unroll
        for (int r = 0; r < NAR; ++r) {
            int lin = tid + 256 * r;
            if (TA) {
                int k = lin >> 5, mq = (lin & 31) * 4;
                float4 v = ra[r];
                v.x = to_tf32(v.x); v.y = to_tf32(v.y); v.z = to_tf32(v.z); v.w = to_tf32(v.w);
                *(float4*)&As[k * ASTR + mq] = v;
            } else {
                int m = lin >> 3, kq = (lin & 7) * 4;
                As[(kq + 0) * ASTR + m] = to_tf32(ra[r].x);
                As[(kq + 1) * ASTR + m] = to_tf32(ra[r].y);
                As[(kq + 2) * ASTR + m] = to_tf32(ra[r].z);
                As[(kq + 3) * ASTR + m] = to_tf32(ra[r].w);
            }
        }
    };
    auto stsB = [&](float* Bs) {
#pragma unroll
        for (int r = 0; r < NBR; ++r) {
            int lin = tid + 256 * r;
            if (TB) {
                constexpr int NQ = BN / 4;
                int k = lin / NQ, nq = (lin % NQ) * 4;
                Bs[(nq + 0) * BSTR + k] = to_tf32(rb[r].x);
                Bs[(nq + 1) * BSTR + k] = to_tf32(rb[r].y);
                Bs[(nq + 2) * BSTR + k] = to_tf32(rb[r].z);
                Bs[(nq + 3) * BSTR + k] = to_tf32(rb[r].w);
            } else {
                int n = lin >> 3, kq = (lin & 7) * 4;
                float4 v = rb[r];
                v.x = to_tf32(v.x); v.y = to_tf32(v.y); v.z = to_tf32(v.z); v.w = to_tf32(v.w);
                *(float4*)&Bs[n * BSTR + kq] = v;
            }
        }
    };

    int warpM = wid & 3, warpN = wid >> 2;
    int mW = warpM * 32, nW = warpN * WN;
    int c4 = lane & 3, r4 = lane >> 2;

    auto compute = [&](const float* As, const float* Bs) {
#pragma unroll
        for (int kk = 0; kk < 32; kk += 8) {
            uint32_t a[2][4];
#pragma unroll
            for (int mf = 0; mf < 2; ++mf) {
                int m = mW + mf * 16 + r4;
                a[mf][0] = f2u(As[(kk + c4) * ASTR + m]);
                a[mf][1] = f2u(As[(kk + c4) * ASTR + m + 8]);
                a[mf][2] = f2u(As[(kk + c4 + 4) * ASTR + m]);
                a[mf][3] = f2u(As[(kk + c4 + 4) * ASTR + m + 8]);
            }
            uint32_t b[NF][2];
#pragma unroll
            for (int nf = 0; nf < NF; ++nf) {
                int n = nW + nf * 8 + r4;
                b[nf][0] = f2u(Bs[n * BSTR + kk + c4]);
                b[nf][1] = f2u(Bs[n * BSTR + kk + c4 + 4]);
            }
#pragma unroll
            for (int mf = 0; mf < 2; ++mf)
#pragma unroll
                for (int nf = 0; nf < NF; ++nf)
                    MMA_TF32(acc[mf][nf], a[mf], b[nf]);
        }
    };

    // prologue: fill stage 0
    ldgA(0); ldgB(0);
    stsA(smf); stsB(smf + AF);
    __syncthreads();

    for (int it = 0; it < nIter; ++it) {
        int cur = it & 1, nxt = cur ^ 1;
        if (it + 1 < nIter) { ldgA((it + 1) * 32); ldgB((it + 1) * 32); }
        compute(smf + cur * STG, smf + cur * STG + AF);
        if (it + 1 < nIter) {
            stsA(smf + nxt * STG); stsB(smf + nxt * STG + AF);
        }
        __syncthreads();
    }

    // ---- epilogue ----
    int mb = z / maskDiv;
#pragma unroll
    for (int mf = 0; mf < 2; ++mf) {
#pragma unroll
        for (int half = 0; half < 2; ++half) {       // c0c1 (row r) / c2c3 (row r+8)
            long m = mBase + mW + mf * 16 + r4 + half * 8;
            float bv = (EPI == 0) ? bias[m] : 0.f;
#pragma unroll
            for (int nf = 0; nf < NF; ++nf) {
                long n = nBase + nW + nf * 8 + 2 * c4;
                float v0 = acc[mf][nf][half * 2 + 0];
                float v1 = acc[mf][nf][half * 2 + 1];
                if (EPI == 0) {
                    v0 += bv; v1 += bv;
                    if (!mask[(long)mb * maskLd + n]) v0 = 0.f;
                    if (!mask[(long)mb * maskLd + n + 1]) v1 = 0.f;
                    if (res) {
                        v0 += res[z * resStride + m * ldc + n];
                        v1 += res[z * resStride + m * ldc + n + 1];
                    }
                } else if (EPI == 1) {
                    v0 = mask[(long)mb * maskLd + n] ? v0 * scale : -1e9f;
                    v1 = mask[(long)mb * maskLd + n + 1] ? v1 * scale : -1e9f;
                }
                float2 o; o.x = v0; o.y = v1;
                *(float2*)&C[m * ldc + n] = o;
            }
        }
    }
}

// ---------------- mask canonicalization (bool-bytes or int32) ----------------
__global__ void canon_mask_kernel(const unsigned char* __restrict__ raw,
                                  unsigned char* __restrict__ out, int n) {
    __shared__ int s_flag;
    if (threadIdx.x == 0) s_flag = 0;
    __syncthreads();
    int local = 0;
    for (int i = threadIdx.x; i < n; i += blockDim.x)
        if ((i & 3) != 0 && raw[i] != 0) local = 1;
    if (local) atomicOr(&s_flag, 1);
    __syncthreads();
    bool is_bool = (s_flag != 0);
    for (int i = threadIdx.x; i < n; i += blockDim.x)
        out[i] = is_bool ? raw[i] : raw[4 * i];
}

// ---------------- weight standardization ----------------
__global__ void ws_kernel(const float* __restrict__ w, float* __restrict__ out, int I) {
    int o = blockIdx.x;
    const float* row = w + (long)o * I;
    float s = 0.f, ss = 0.f;
    for (int i = threadIdx.x; i < I; i += 256) {
        float v = row[i];
        s += v; ss += v * v;
    }
#pragma unroll
    for (int off = 16; off; off >>= 1) {
        s += __shfl_xor_sync(0xFFFFFFFFu, s, off);
        ss += __shfl_xor_sync(0xFFFFFFFFu, ss, off);
    }
    __shared__ float sh[16];
    int wid = threadIdx.x >> 5;
    if ((threadIdx.x & 31) == 0) { sh[wid] = s; sh[8 + wid] = ss; }
    __syncthreads();
    if (threadIdx.x == 0) {
        float ts = 0.f, tss = 0.f;
        for (int i = 0; i < 8; i++) { ts += sh[i]; tss += sh[8 + i]; }
        float mu = ts / (float)I;
        float var = tss / (float)I - mu * mu;
        sh[0] = mu; sh[1] = rsqrtf(var + EPSV);
    }
    __syncthreads();
    float mu = sh[0], inv = sh[1];
    for (int i = threadIdx.x; i < I; i += 256)
        out[(long)o * I + i] = (row[i] - mu) * inv;
}

// ---------------- per-head LayerNorm over dh=64 ----------------
__global__ void ln_kernel(float* __restrict__ buf, const float* __restrict__ g,
                          const float* __restrict__ bt, int L) {
    int bh = blockIdx.y;
    int l = blockIdx.x * blockDim.x + threadIdx.x;
    float* base = buf + (long)bh * DH * L + l;
    float vals[DH];
    float s = 0.f, ss = 0.f;
#pragma unroll
    for (int d = 0; d < DH; d++) {
        float v = base[(long)d * L];
        vals[d] = v;
        s += v; ss += v * v;
    }
    float mu = s * (1.f / DH);
    float var = ss * (1.f / DH) - mu * mu;
    float inv = rsqrtf(var + EPSV);
#pragma unroll
    for (int d = 0; d < DH; d++)
        base[(long)d * L] = (vals[d] - mu) * inv * g[d] + bt[d];
}

// ---------------- softmax over T per (b,h,s) row ----------------
__global__ void softmax_kernel(float* __restrict__ sc,
                               const unsigned char* __restrict__ mctx) {
    long row = blockIdx.x;
    int b = (int)(row / (NH * SLEN));
    int s = (int)(row % SLEN);
    float* p = sc + row * (long)TLEN;
    int t = threadIdx.x;
    float v[8];
    float m = -3.0e38f;
#pragma unroll
    for (int r = 0; r < 8; r++) {
        v[r] = p[t + r * 128];
        m = fmaxf(m, v[r]);
    }
#pragma unroll
    for (int off = 16; off; off >>= 1)
        m = fmaxf(m, __shfl_xor_sync(0xFFFFFFFFu, m, off));
    __shared__ float sm[4], ssum[4];
    if ((t & 31) == 0) sm[t >> 5] = m;
    __syncthreads();
    m = fmaxf(fmaxf(sm[0], sm[1]), fmaxf(sm[2], sm[3]));
    float sum = 0.f;
#pragma unroll
    for (int r = 0; r < 8; r++) {
        v[r] = expf(v[r] - m);
        sum += v[r];
    }
#pragma unroll
    for (int off = 16; off; off >>= 1)
        sum += __shfl_xor_sync(0xFFFFFFFFu, sum, off);
    if ((t & 31) == 0) ssum[t >> 5] = sum;
    __syncthreads();
    sum = ssum[0] + ssum[1] + ssum[2] + ssum[3];
    float inv = (mctx[(long)b * SLEN + s] && sum > 0.f) ? (1.f / sum) : 0.f;
#pragma unroll
    for (int r = 0; r < 8; r++)
        p[t + r * 128] = v[r] * inv;
}

// ---------------- launch ----------------
extern "C" void kernel_launch(void* const* d_in, const int* in_sizes, int n_in,
                              void* d_out, int out_size) {
    const float* x = (const float*)d_in[0];
    const float* ctx = (const float*)d_in[1];
    const unsigned char* mask_raw = (const unsigned char*)d_in[2];
    const unsigned char* mctx_raw = (const unsigned char*)d_in[3];
    const float* qw = (const float*)d_in[4];
    const float* qb = (const float*)d_in[5];
    const float* kw = (const float*)d_in[6];
    const float* kb = (const float*)d_in[7];
    const float* vw = (const float*)d_in[8];
    const float* vb = (const float*)d_in[9];
    const float* ow = (const float*)d_in[10];
    const float* ob = (const float*)d_in[11];
    const float* gq = (const float*)d_in[12];
    const float* bq = (const float*)d_in[13];
    const float* gk = (const float*)d_in[14];
    const float* bk = (const float*)d_in[15];
    const float* gv = (const float*)d_in[16];
    const float* bv = (const float*)d_in[17];
    float* out = (float*)d_out;

    float *wnq, *wnk, *wnv, *wno, *qbuf, *kbuf, *vbuf, *pbuf, *abuf;
    unsigned char *mask, *mctx;
    cudaGetSymbolAddress((void**)&wnq, g_wnq);
    cudaGetSymbolAddress((void**)&wnk, g_wnk);
    cudaGetSymbolAddress((void**)&wnv, g_wnv);
    cudaGetSymbolAddress((void**)&wno, g_wno);
    cudaGetSymbolAddress((void**)&qbuf, g_q);
    cudaGetSymbolAddress((void**)&kbuf, g_k);
    cudaGetSymbolAddress((void**)&vbuf, g_v);
    cudaGetSymbolAddress((void**)&pbuf, g_p);
    cudaGetSymbolAddress((void**)&abuf, g_att);
    cudaGetSymbolAddress((void**)&mask, g_mask);
    cudaGetSymbolAddress((void**)&mctx, g_mctx);

    // dynamic smem: 2 stages of (32*136 + BN*36) floats
    const int SM128 = 2 * (32 * 136 + 128 * 36) * 4;   // 71680
    const int SM64 = 2 * (32 * 136 + 64 * 36) * 4;     // 53248
    cudaFuncSetAttribute((const void*)mma_gemm<0, false, true, 128>,
                         cudaFuncAttributeMaxDynamicSharedMemorySize, SM128);
    cudaFuncSetAttribute((const void*)mma_gemm<1, true, true, 128>,
                         cudaFuncAttributeMaxDynamicSharedMemorySize, SM128);
    cudaFuncSetAttribute((const void*)mma_gemm<2, true, false, 64>,
                         cudaFuncAttributeMaxDynamicSharedMemorySize, SM64);
    cudaFuncSetAttribute((const void*)mma_gemm<0, false, false, 128>,
                         cudaFuncAttributeMaxDynamicSharedMemorySize, SM128);

    // 0. canonicalize masks
    canon_mask_kernel<<<1, 256>>>(mask_raw, mask, BATCH * TLEN);
    canon_mask_kernel<<<1, 256>>>(mctx_raw, mctx, BATCH * SLEN);

    // 1. weight standardization
    ws_kernel<<<EDIM, 256>>>(qw, wnq, EDIM);
    ws_kernel<<<EDIM, 256>>>(kw, wnk, CDIM);
    ws_kernel<<<EDIM, 256>>>(vw, wnv, CDIM);
    ws_kernel<<<EDIM, 256>>>(ow, wno, EDIM);

    // 2. QKV projections: C[e,t] = wn[e,:]·src[:,t], bias + col-mask
    dim3 gq_(TLEN / 128, EDIM / 128, BATCH);
    mma_gemm<0, false, true, 128><<<gq_, 256, SM128>>>(
        wnq, 0, EDIM, x, (long)EDIM * TLEN, TLEN,
        qbuf, 1, (long)EDIM * TLEN, 0, TLEN, EDIM,
        qb, mask, 1, TLEN, nullptr, 0, 1.f);
    mma_gemm<0, false, true, 128><<<gq_, 256, SM128>>>(
        wnk, 0, CDIM, ctx, (long)CDIM * SLEN, SLEN,
        kbuf, 1, (long)EDIM * SLEN, 0, SLEN, CDIM,
        kb, mctx, 1, SLEN, nullptr, 0, 1.f);
    mma_gemm<0, false, true, 128><<<gq_, 256, SM128>>>(
        wnv, 0, CDIM, ctx, (long)CDIM * SLEN, SLEN,
        vbuf, 1, (long)EDIM * SLEN, 0, SLEN, CDIM,
        vb, mctx, 1, SLEN, nullptr, 0, 1.f);

    // 3. per-head LayerNorm over dh
    dim3 gln(TLEN / 128, BATCH * NH);
    ln_kernel<<<gln, 128>>>(qbuf, gq, bq, TLEN);
    ln_kernel<<<gln, 128>>>(kbuf, gk, bk, SLEN);
    ln_kernel<<<gln, 128>>>(vbuf, gv, bv, SLEN);

    // 4. scores[s,t] = sum_d k[d,s] q[d,t] / 256; t-mask -> -1e9
    dim3 gsc(TLEN / 128, SLEN / 128, BATCH * NH);
    mma_gemm<1, true, true, 128><<<gsc, 256, SM128>>>(
        kbuf, (long)DH * SLEN, SLEN, qbuf, (long)DH * TLEN, TLEN,
        pbuf, 1, (long)SLEN * TLEN, 0, TLEN, DH,
        nullptr, mask, NH, TLEN, nullptr, 0, 1.f / 256.f);

    // 5. softmax over T per (b,h,s) row, then ctx-mask zeroing
    softmax_kernel<<<BATCH * NH * SLEN, 128>>>(pbuf, mctx);

    // 6. attT[t, d] = sum_s P[s,t] v[d,s]  (M=T tiles, N=DH=64)
    dim3 gav(1, TLEN / 128, BATCH * NH);
    mma_gemm<2, true, false, 64><<<gav, 256, SM64>>>(
        pbuf, (long)SLEN * TLEN, TLEN, vbuf, (long)DH * SLEN, SLEN,
        abuf, NH, (long)TLEN * EDIM, DH, EDIM, SLEN,
        nullptr, mask, 1, TLEN, nullptr, 0, 1.f);

    // 7. output projection: C[e,t] = wno[e,:]·attT[t,:] + bias, mask, + x
    mma_gemm<0, false, false, 128><<<gq_, 256, SM128>>>(
        wno, 0, EDIM, abuf, (long)TLEN * EDIM, EDIM,
        out, 1, (long)EDIM * TLEN, 0, TLEN, EDIM,
        ob, mask, 1, TLEN, x, (long)EDIM * TLEN, 1.f);
}

// round 5
// speedup vs baseline: 2.5430x; 1.5209x over previous
#include <cuda_runtime.h>
#include <cstdint>

#define BATCH 4
#define EDIM 1024
#define CDIM 768
#define TLEN 1024
#define SLEN 1024
#define NH 16
#define DH 64
#define EPSV 1e-5f

// ---------------- scratch (static device globals; no allocation) ----------------
__device__ float g_wnq[EDIM * EDIM];
__device__ float g_wnkv[2 * EDIM * CDIM];               // [wnk ; wnv]
__device__ float g_wno[EDIM * EDIM];
__device__ float g_kvb[2 * EDIM];                       // [kb ; vb]
__device__ float g_xr[BATCH * EDIM * TLEN];             // tf32-rounded x
__device__ float g_cr[BATCH * CDIM * SLEN];             // tf32-rounded ctx
__device__ float g_q[BATCH * EDIM * TLEN];
__device__ float g_kv[(long)BATCH * 2 * EDIM * SLEN];   // [B][2E][S]: k rows 0..E-1, v rows E..2E-1
__device__ float g_p[(long)BATCH * NH * SLEN * TLEN];   // 256 MB score/prob scratch
__device__ float g_att[BATCH * EDIM * TLEN];            // att^T: [B][T][E]
__device__ unsigned char g_mask[BATCH * TLEN];
__device__ unsigned char g_mctx[BATCH * SLEN];

__device__ __forceinline__ float to_tf32(float x) {
    float r;
    asm("cvt.rna.tf32.f32 %0, %1;" : "=f"(r) : "f"(x));
    return r;
}
__device__ __forceinline__ uint32_t f2u(float x) { return __float_as_uint(x); }
__device__ __forceinline__ uint32_t smem_u32(const void* p) {
    uint32_t a;
    asm("{ .reg .u64 t; cvta.to.shared.u64 t, %1; cvt.u32.u64 %0, t; }" : "=r"(a) : "l"(p));
    return a;
}
#define CP16(dst, src) asm volatile("cp.async.cg.shared.global [%0], [%1], 16;" :: "r"(dst), "l"(src))
#define CPCOMMIT()     asm volatile("cp.async.commit_group;" ::: "memory")
#define CPWAIT(N)      asm volatile("cp.async.wait_group %0;" :: "n"(N) : "memory")

#define MMA_TF32(d, a, b) \
    asm volatile("mma.sync.aligned.m16n8k8.row.col.f32.tf32.tf32.f32 " \
                 "{%0,%1,%2,%3}, {%4,%5,%6,%7}, {%8,%9}, {%0,%1,%2,%3};" \
                 : "+f"((d)[0]), "+f"((d)[1]), "+f"((d)[2]), "+f"((d)[3]) \
                 : "r"((a)[0]), "r"((a)[1]), "r"((a)[2]), "r"((a)[3]), \
                   "r"((b)[0]), "r"((b)[1]))

// ================= mma.sync TF32 GEMM (cp.async 3-stage, conflict-free layouts) =======
// C[m,n] = sum_k A'[m,k] * B'[n,k]
//   A' from src [m,k] (TA=false, smem [m][k] str 36) or [k,m] (TA=true, smem [k][m] str 136)
//   B' from src [n,k] (TB=false, smem [n][k] str 36) or [k,n] (TB=true, smem [k][n] str 136)
// Operands must be pre-rounded to tf32 by producers.
// EPI 0: conv (bias + col-mask->0 + optional residual)
// EPI 1: score (mask ? c*scale : -1e9)
// EPI 2: plain + tf32-round on store
template <int EPI, bool TA, bool TB, int BN>
__global__ __launch_bounds__(256) void mma_gemm(
    const float* __restrict__ A0, int aDiv, long aStrZa, long aStrZb, int lda,
    const float* __restrict__ B0, int bDiv, long bStrZa, long bStrZb, int ldb,
    float* __restrict__ C0, int cDiv, long cStrZa, long cStrZb, int ldc,
    int K,
    const float* __restrict__ bias,
    const unsigned char* __restrict__ mask, int maskDiv, int maskLd,
    const float* __restrict__ res, long resStride, float scale)
{
    constexpr int BM = 128;
    constexpr int AST = TA ? 136 : 36;
    constexpr int AFL = TA ? 32 * 136 : BM * 36;
    constexpr int BST = TB ? 136 : 36;
    constexpr int BFL = TB ? 32 * 136 : BN * 36;
    constexpr int STG = AFL + BFL;
    constexpr int NS = 3;
    constexpr int WN = BN / 2;
    constexpr int NF = WN / 8;

    extern __shared__ float smf[];
    uint32_t sbase = smem_u32(smf);
    int tid = threadIdx.x, wid = tid >> 5, lane = tid & 31;
    int z = blockIdx.z;
    const float* A = A0 + (z / aDiv) * aStrZa + (z % aDiv) * aStrZb;
    const float* B = B0 + (z / bDiv) * bStrZa + (z % bDiv) * bStrZb;
    float* C = C0 + (z / cDiv) * cStrZa + (z % cDiv) * cStrZb;
    long mBase = (long)blockIdx.y * BM, nBase = (long)blockIdx.x * BN;

    float acc[2][NF][4];
#pragma unroll
    for (int i = 0; i < 2; ++i)
#pragma unroll
        for (int j = 0; j < NF; ++j)
#pragma unroll
            for (int t = 0; t < 4; ++t) acc[i][j][t] = 0.f;

    int nIter = K / 32;

    auto issue = [&](int stage, int k0) {
        uint32_t aoff = sbase + stage * STG * 4;
        if (TA) {
#pragma unroll
            for (int r = 0; r < 4; ++r) {
                int lin = tid + 256 * r;
                int k = lin >> 5, mq = (lin & 31) * 4;
                CP16(aoff + (k * 136 + mq) * 4, &A[(long)(k0 + k) * lda + mBase + mq]);
            }
        } else {
#pragma unroll
            for (int r = 0; r < BM / 32; ++r) {
                int lin = tid + 256 * r;
                int m = lin >> 3, kq = (lin & 7) * 4;
                CP16(aoff + (m * 36 + kq) * 4, &A[(mBase + m) * (long)lda + k0 + kq]);
            }
        }
        uint32_t boff = sbase + (stage * STG + AFL) * 4;
        if (TB) {
#pragma unroll
            for (int r = 0; r < 4; ++r) {
                int lin = tid + 256 * r;
                int k = lin >> 5, nq = (lin & 31) * 4;
                CP16(boff + (k * 136 + nq) * 4, &B[(long)(k0 + k) * ldb + nBase + nq]);
            }
        } else {
#pragma unroll
            for (int r = 0; r < BN / 32; ++r) {
                int lin = tid + 256 * r;
                int n = lin >> 3, kq = (lin & 7) * 4;
                CP16(boff + (n * 36 + kq) * 4, &B[(nBase + n) * (long)ldb + k0 + kq]);
            }
        }
    };

    int warpM = wid & 3, warpN = wid >> 2;
    int mW = warpM * 32, nW = warpN * WN;
    int c4 = lane & 3, r4 = lane >> 2;

    auto compute = [&](int stage) {
        const float* As = smf + stage * STG;
        const float* Bs = As + AFL;
#pragma unroll
        for (int kk = 0; kk < 32; kk += 8) {
            uint32_t a[2][4];
#pragma unroll
            for (int mf = 0; mf < 2; ++mf) {
                int m = mW + mf * 16 + r4;
                if (TA) {
                    a[mf][0] = f2u(As[(kk + c4) * 136 + m]);
                    a[mf][1] = f2u(As[(kk + c4) * 136 + m + 8]);
                    a[mf][2] = f2u(As[(kk + c4 + 4) * 136 + m]);
                    a[mf][3] = f2u(As[(kk + c4 + 4) * 136 + m + 8]);
                } else {
                    a[mf][0] = f2u(As[m * 36 + kk + c4]);
                    a[mf][1] = f2u(As[(m + 8) * 36 + kk + c4]);
                    a[mf][2] = f2u(As[m * 36 + kk + c4 + 4]);
                    a[mf][3] = f2u(As[(m + 8) * 36 + kk + c4 + 4]);
                }
            }
            uint32_t b[NF][2];
#pragma unroll
            for (int nf = 0; nf < NF; ++nf) {
                int n = nW + nf * 8 + r4;
                if (TB) {
                    b[nf][0] = f2u(Bs[(kk + c4) * 136 + n]);
                    b[nf][1] = f2u(Bs[(kk + c4 + 4) * 136 + n]);
                } else {
                    b[nf][0] = f2u(Bs[n * 36 + kk + c4]);
                    b[nf][1] = f2u(Bs[n * 36 + kk + c4 + 4]);
                }
            }
#pragma unroll
            for (int mf = 0; mf < 2; ++mf)
#pragma unroll
                for (int nf = 0; nf < NF; ++nf)
                    MMA_TF32(acc[mf][nf], a[mf], b[nf]);
        }
    };

    // prologue: prefill NS-1 stages
    for (int s = 0; s < NS - 1; ++s) {
        if (s < nIter) issue(s, s * 32);
        CPCOMMIT();
    }
    for (int it = 0; it < nIter; ++it) {
        CPWAIT(NS - 2);
        __syncthreads();
        compute(it % NS);
        __syncthreads();
        int nx = it + NS - 1;
        if (nx < nIter) issue(nx % NS, nx * 32);
        CPCOMMIT();
    }

    // ---- epilogue ----
    int mb = z / maskDiv;
#pragma unroll
    for (int mf = 0; mf < 2; ++mf) {
#pragma unroll
        for (int half = 0; half < 2; ++half) {
            long m = mBase + mW + mf * 16 + r4 + half * 8;
            float bv = (EPI == 0) ? bias[m] : 0.f;
#pragma unroll
            for (int nf = 0; nf < NF; ++nf) {
                long n = nBase + nW + nf * 8 + 2 * c4;
                float v0 = acc[mf][nf][half * 2 + 0];
                float v1 = acc[mf][nf][half * 2 + 1];
                if (EPI == 0) {
                    v0 += bv; v1 += bv;
                    if (!mask[(long)mb * maskLd + n]) v0 = 0.f;
                    if (!mask[(long)mb * maskLd + n + 1]) v1 = 0.f;
                    if (res) {
                        v0 += res[z * resStride + m * ldc + n];
                        v1 += res[z * resStride + m * ldc + n + 1];
                    }
                } else if (EPI == 1) {
                    v0 = mask[(long)mb * maskLd + n] ? v0 * scale : -1e9f;
                    v1 = mask[(long)mb * maskLd + n + 1] ? v1 * scale : -1e9f;
                } else {
                    v0 = to_tf32(v0); v1 = to_tf32(v1);
                }
                float2 o; o.x = v0; o.y = v1;
                *(float2*)&C[m * ldc + n] = o;
            }
        }
    }
}

// ---------------- mask canonicalization (bool-bytes or int32) ----------------
__global__ void canon_mask_kernel(const unsigned char* __restrict__ raw,
                                  unsigned char* __restrict__ out, int n) {
    __shared__ int s_flag;
    if (threadIdx.x == 0) s_flag = 0;
    __syncthreads();
    int local = 0;
    for (int i = threadIdx.x; i < n; i += blockDim.x)
        if ((i & 3) != 0 && raw[i] != 0) local = 1;
    if (local) atomicOr(&s_flag, 1);
    __syncthreads();
    bool is_bool = (s_flag != 0);
    for (int i = threadIdx.x; i < n; i += blockDim.x)
        out[i] = is_bool ? raw[i] : raw[4 * i];
}

// ---------------- tf32 rounding copy ----------------
__global__ void round_kernel(const float* __restrict__ in, float* __restrict__ out, int n4) {
    int i = blockIdx.x * blockDim.x + threadIdx.x;
    if (i < n4) {
        float4 v = ((const float4*)in)[i];
        v.x = to_tf32(v.x); v.y = to_tf32(v.y); v.z = to_tf32(v.z); v.w = to_tf32(v.w);
        ((float4*)out)[i] = v;
    }
}

// ---------------- bias concat ----------------
__global__ void concat_bias_kernel(const float* __restrict__ a, const float* __restrict__ b,
                                   float* __restrict__ out) {
    int i = blockIdx.x * blockDim.x + threadIdx.x;
    out[i] = (i < EDIM) ? a[i] : b[i - EDIM];
}

// ---------------- weight standardization (writes tf32-rounded) ----------------
__global__ void ws_kernel(const float* __restrict__ w, float* __restrict__ out, int I) {
    int o = blockIdx.x;
    const float* row = w + (long)o * I;
    float s = 0.f, ss = 0.f;
    for (int i = threadIdx.x; i < I; i += 256) {
        float v = row[i];
        s += v; ss += v * v;
    }
#pragma unroll
    for (int off = 16; off; off >>= 1) {
        s += __shfl_xor_sync(0xFFFFFFFFu, s, off);
        ss += __shfl_xor_sync(0xFFFFFFFFu, ss, off);
    }
    __shared__ float sh[16];
    int wid = threadIdx.x >> 5;
    if ((threadIdx.x & 31) == 0) { sh[wid] = s; sh[8 + wid] = ss; }
    __syncthreads();
    if (threadIdx.x == 0) {
        float ts = 0.f, tss = 0.f;
        for (int i = 0; i < 8; i++) { ts += sh[i]; tss += sh[8 + i]; }
        float mu = ts / (float)I;
        float var = tss / (float)I - mu * mu;
        sh[0] = mu; sh[1] = rsqrtf(var + EPSV);
    }
    __syncthreads();
    float mu = sh[0], inv = sh[1];
    for (int i = threadIdx.x; i < I; i += 256)
        out[(long)o * I + i] = to_tf32((row[i] - mu) * inv);
}

// ---------------- per-head LayerNorm over dh=64 (writes tf32-rounded) ----------------
__global__ void ln_kernel(float* __restrict__ buf, long zStr,
                          const float* __restrict__ g, const float* __restrict__ bt, int L) {
    int bh = blockIdx.y;
    int l = blockIdx.x * blockDim.x + threadIdx.x;
    float* base = buf + (long)(bh / NH) * zStr + (long)(bh % NH) * DH * L + l;
    float vals[DH];
    float s = 0.f, ss = 0.f;
#pragma unroll
    for (int d = 0; d < DH; d++) {
        float v = base[(long)d * L];
        vals[d] = v;
        s += v; ss += v * v;
    }
    float mu = s * (1.f / DH);
    float var = ss * (1.f / DH) - mu * mu;
    float inv = rsqrtf(var + EPSV);
#pragma unroll
    for (int d = 0; d < DH; d++)
        base[(long)d * L] = to_tf32((vals[d] - mu) * inv * g[d] + bt[d]);
}

// ---------------- softmax over T per (b,h,s) row (writes tf32-rounded) ----------------
__global__ void softmax_kernel(float* __restrict__ sc,
                               const unsigned char* __restrict__ mctx) {
    long row = blockIdx.x;
    int b = (int)(row / (NH * SLEN));
    int s = (int)(row % SLEN);
    float* p = sc + row * (long)TLEN;
    int t = threadIdx.x;
    float v[8];
    float m = -3.0e38f;
#pragma unroll
    for (int r = 0; r < 8; r++) {
        v[r] = p[t + r * 128];
        m = fmaxf(m, v[r]);
    }
#pragma unroll
    for (int off = 16; off; off >>= 1)
        m = fmaxf(m, __shfl_xor_sync(0xFFFFFFFFu, m, off));
    __shared__ float sm[4], ssum[4];
    if ((t & 31) == 0) sm[t >> 5] = m;
    __syncthreads();
    m = fmaxf(fmaxf(sm[0], sm[1]), fmaxf(sm[2], sm[3]));
    float sum = 0.f;
#pragma unroll
    for (int r = 0; r < 8; r++) {
        v[r] = expf(v[r] - m);
        sum += v[r];
    }
#pragma unroll
    for (int off = 16; off; off >>= 1)
        sum += __shfl_xor_sync(0xFFFFFFFFu, sum, off);
    if ((t & 31) == 0) ssum[t >> 5] = sum;
    __syncthreads();
    sum = ssum[0] + ssum[1] + ssum[2] + ssum[3];
    float inv = (mctx[(long)b * SLEN + s] && sum > 0.f) ? (1.f / sum) : 0.f;
#pragma unroll
    for (int r = 0; r < 8; r++)
        p[t + r * 128] = to_tf32(v[r] * inv);
}

// ---------------- launch ----------------
extern "C" void kernel_launch(void* const* d_in, const int* in_sizes, int n_in,
                              void* d_out, int out_size) {
    const float* x = (const float*)d_in[0];
    const float* ctx = (const float*)d_in[1];
    const unsigned char* mask_raw = (const unsigned char*)d_in[2];
    const unsigned char* mctx_raw = (const unsigned char*)d_in[3];
    const float* qw = (const float*)d_in[4];
    const float* qb = (const float*)d_in[5];
    const float* kw = (const float*)d_in[6];
    const float* kb = (const float*)d_in[7];
    const float* vw = (const float*)d_in[8];
    const float* vb = (const float*)d_in[9];
    const float* ow = (const float*)d_in[10];
    const float* ob = (const float*)d_in[11];
    const float* gq = (const float*)d_in[12];
    const float* bq = (const float*)d_in[13];
    const float* gk = (const float*)d_in[14];
    const float* bk = (const float*)d_in[15];
    const float* gv = (const float*)d_in[16];
    const float* bv = (const float*)d_in[17];
    float* out = (float*)d_out;

    float *wnq, *wnkv, *wno, *kvb, *xr, *cr, *qbuf, *kvbuf, *pbuf, *abuf;
    unsigned char *mask, *mctx;
    cudaGetSymbolAddress((void**)&wnq, g_wnq);
    cudaGetSymbolAddress((void**)&wnkv, g_wnkv);
    cudaGetSymbolAddress((void**)&wno, g_wno);
    cudaGetSymbolAddress((void**)&kvb, g_kvb);
    cudaGetSymbolAddress((void**)&xr, g_xr);
    cudaGetSymbolAddress((void**)&cr, g_cr);
    cudaGetSymbolAddress((void**)&qbuf, g_q);
    cudaGetSymbolAddress((void**)&kvbuf, g_kv);
    cudaGetSymbolAddress((void**)&pbuf, g_p);
    cudaGetSymbolAddress((void**)&abuf, g_att);
    cudaGetSymbolAddress((void**)&mask, g_mask);
    cudaGetSymbolAddress((void**)&mctx, g_mctx);

    // dynamic smem (3 stages)
    const int SM_QKV = 3 * (128 * 36 + 32 * 136) * 4;   // 107520
    const int SM_SC = 3 * (32 * 136 + 32 * 136) * 4;    // 104448
    const int SM_AV = 3 * (32 * 136 + 64 * 36) * 4;     // 79872
    const int SM_OP = 3 * (128 * 36 + 128 * 36) * 4;    // 110592
    cudaFuncSetAttribute((const void*)mma_gemm<0, false, true, 128>,
                         cudaFuncAttributeMaxDynamicSharedMemorySize, SM_QKV);
    cudaFuncSetAttribute((const void*)mma_gemm<1, true, true, 128>,
                         cudaFuncAttributeMaxDynamicSharedMemorySize, SM_SC);
    cudaFuncSetAttribute((const void*)mma_gemm<2, true, false, 64>,
                         cudaFuncAttributeMaxDynamicSharedMemorySize, SM_AV);
    cudaFuncSetAttribute((const void*)mma_gemm<0, false, false, 128>,
                         cudaFuncAttributeMaxDynamicSharedMemorySize, SM_OP);

    // 0. canonicalize masks; round inputs; concat kv bias
    canon_mask_kernel<<<1, 256>>>(mask_raw, mask, BATCH * TLEN);
    canon_mask_kernel<<<1, 256>>>(mctx_raw, mctx, BATCH * SLEN);
    round_kernel<<<(BATCH * EDIM * TLEN / 4 + 255) / 256, 256>>>(x, xr, BATCH * EDIM * TLEN / 4);
    round_kernel<<<(BATCH * CDIM * SLEN / 4 + 255) / 256, 256>>>(ctx, cr, BATCH * CDIM * SLEN / 4);
    concat_bias_kernel<<<8, 256>>>(kb, vb, kvb);

    // 1. weight standardization (rounded)
    ws_kernel<<<EDIM, 256>>>(qw, wnq, EDIM);
    ws_kernel<<<EDIM, 256>>>(kw, wnkv, CDIM);
    ws_kernel<<<EDIM, 256>>>(vw, wnkv + EDIM * CDIM, CDIM);
    ws_kernel<<<EDIM, 256>>>(ow, wno, EDIM);

    // 2a. Q projection: q[e,t] = wnq[e,:]·xr[:,t] + qb, col-mask
    dim3 gq_(TLEN / 128, EDIM / 128, BATCH);
    mma_gemm<0, false, true, 128><<<gq_, 256, SM_QKV>>>(
        wnq, 1, 0, 0, EDIM,
        xr, 1, (long)EDIM * TLEN, 0, TLEN,
        qbuf, 1, (long)EDIM * TLEN, 0, TLEN,
        EDIM, qb, mask, 1, TLEN, nullptr, 0, 1.f);
    // 2b. merged K|V projection: kv[m,s], m in [0,2E)
    dim3 gkv(SLEN / 128, 2 * EDIM / 128, BATCH);
    mma_gemm<0, false, true, 128><<<gkv, 256, SM_QKV>>>(
        wnkv, 1, 0, 0, CDIM,
        cr, 1, (long)CDIM * SLEN, 0, SLEN,
        kvbuf, 1, (long)2 * EDIM * SLEN, 0, SLEN,
        CDIM, kvb, mctx, 1, SLEN, nullptr, 0, 1.f);

    // 3. per-head LayerNorm over dh (rounded writes)
    dim3 gln(TLEN / 128, BATCH * NH);
    ln_kernel<<<gln, 128>>>(qbuf, (long)EDIM * TLEN, gq, bq, TLEN);
    ln_kernel<<<gln, 128>>>(kvbuf, (long)2 * EDIM * SLEN, gk, bk, SLEN);
    ln_kernel<<<gln, 128>>>(kvbuf + EDIM * SLEN, (long)2 * EDIM * SLEN, gv, bv, SLEN);

    // 4. scores[s,t] = sum_d k[d,s] q[d,t] / 256; t-mask -> -1e9
    dim3 gsc(TLEN / 128, SLEN / 128, BATCH * NH);
    mma_gemm<1, true, true, 128><<<gsc, 256, SM_SC>>>(
        kvbuf, NH, (long)2 * EDIM * SLEN, (long)DH * SLEN, SLEN,
        qbuf, NH, (long)EDIM * TLEN, (long)DH * TLEN, TLEN,
        pbuf, 1, (long)SLEN * TLEN, 0, TLEN,
        DH, nullptr, mask, NH, TLEN, nullptr, 0, 1.f / 256.f);

    // 5. softmax over T per (b,h,s) row, ctx-mask zeroing, rounded P
    softmax_kernel<<<BATCH * NH * SLEN, 128>>>(pbuf, mctx);

    // 6. attT[t,d] = sum_s P[s,t] v[d,s]  (M=T tiles, N=DH=64), rounded store
    dim3 gav(1, TLEN / 128, BATCH * NH);
    mma_gemm<2, true, false, 64><<<gav, 256, SM_AV>>>(
        pbuf, 1, (long)SLEN * TLEN, 0, TLEN,
        kvbuf + EDIM * SLEN, NH, (long)2 * EDIM * SLEN, (long)DH * SLEN, SLEN,
        abuf, NH, (long)TLEN * EDIM, DH, EDIM,
        SLEN, nullptr, mask, 1, TLEN, nullptr, 0, 1.f);

    // 7. output projection: C[e,t] = wno[e,:]·attT[t,:] + ob, mask, + x
    mma_gemm<0, false, false, 128><<<gq_, 256, SM_OP>>>(
        wno, 1, 0, 0, EDIM,
        abuf, 1, (long)TLEN * EDIM, 0, EDIM,
        out, 1, (long)EDIM * TLEN, 0, TLEN,
        EDIM, ob, mask, 1, TLEN, x, (long)EDIM * TLEN, 1.f);
}